// round 2
// baseline (speedup 1.0000x reference)
#include <cuda_runtime.h>
#include <math.h>

#define NLEV   16
#define NDENSE 12
#define NCONS  4
#define TSIZE  524288
#define HPRIME 2654435761u
#define HMASK  524287u
#define BLK    256

// Dense-level resolutions (verified: float32 np.power chain margins are all >>
// the accumulated 1-2 ulp error; worst is level 7 at 153.988).
__device__ __constant__ int   RESD[NDENSE] = {16,22,30,42,58,80,111,153,212,294,406,561};
__device__ __constant__ float GSD[NDENSE] = {
    (float)(2048.0/16.0),  (float)(2048.0/22.0),  (float)(2048.0/30.0),
    (float)(2048.0/42.0),  (float)(2048.0/58.0),  (float)(2048.0/80.0),
    (float)(2048.0/111.0), (float)(2048.0/153.0), (float)(2048.0/212.0),
    (float)(2048.0/294.0), (float)(2048.0/406.0), (float)(2048.0/561.0)
};

// Consistent-hash level params recovered exactly from lengths (levels 14/15 sit
// within float32 noise of a floor boundary, so they cannot be hardcoded).
struct ConsParams { int res[NCONS]; int n[NCONS]; float gs[NCONS]; };
__device__ ConsParams g_cp;

__global__ void setup_kernel(const int* __restrict__ lengths, int L)
{
    if (threadIdx.x == 0 && blockIdx.x == 0) {
        for (int i = 0; i < NCONS; i++) {
            int li  = (i < L) ? i : (L - 1);
            int len = lengths[li];                    // (res+1)^2
            int res = (int)(sqrt((double)len) + 0.5) - 1;
            g_cp.res[i] = res;
            g_cp.n[i]   = len;
            g_cp.gs[i]  = (float)(2048.0 / (double)res);
        }
    }
}

// XLA:GPU emits approximate full-range division (div.full.f32) for f32 divide.
// Replicating it is REQUIRED for bit-exact bl = floor(x/gs): ~4% of divisions
// differ from IEEE div.rn in the last ulp, flipping floor() at cell boundaries.
__device__ __forceinline__ float div_full(float a, float b)
{
    float r;
    asm("div.full.f32 %0, %1, %2;" : "=f"(r) : "f"(a), "f"(b));
    return r;
}

// Exact replica of jnp.searchsorted(tk_row, 2h) -> where(k==n,0,k) -> tv[k].
// Only reached when a corner coordinate exceeds res (rounding edge case).
__device__ __forceinline__ int cons_lookup(const int* __restrict__ tk,
                                           const int* __restrict__ tv,
                                           long long rowoff, int n, unsigned h)
{
    int q  = 2 * (int)h;
    int lo = 0, hi = n;
    while (lo < hi) {
        int mid = (lo + hi) >> 1;
        if (__ldg(tk + rowoff + mid) < q) lo = mid + 1; else hi = mid;
    }
    if (lo == n) lo = 0;
    return __ldg(tv + rowoff + lo);
}

__global__ __launch_bounds__(BLK)
void hashgrid_kernel(const float* __restrict__ x,
                     const float* __restrict__ tables,
                     const int*   __restrict__ tk,
                     const int*   __restrict__ tv,
                     int maxP,
                     float* __restrict__ out,
                     int npts)
{
    // 33-float padded rows: conflict-free writes and conflict-free transpose reads.
    __shared__ float s_f[BLK * 33];

    const int tid   = threadIdx.x;
    const int p     = blockIdx.x * BLK + tid;
    const bool valid = (p < npts);
    const int pl    = valid ? p : (npts - 1);

    const float2 xv = __ldg((const float2*)x + pl);
    const float x0 = xv.x, x1 = xv.y;
    const size_t idxbase = (size_t)npts * 32;

    // ---------------- dense levels 0..11 ----------------
#pragma unroll
    for (int lvl = 0; lvl < NDENSE; lvl++) {
        const int   res = RESD[lvl];
        const float gs  = GSD[lvl];

        float q0  = div_full(x0, gs);
        float q1  = div_full(x1, gs);
        float b0f = floorf(q0), b1f = floorf(q1);
        int   b0  = (int)b0f,   b1  = (int)b1f;
        float mn0 = b0f * gs,   mn1 = b1f * gs;
        float w0  = __fdiv_rn(x0 - mn0, (mn0 + gs) - mn0);
        float w1  = __fdiv_rn(x1 - mn1, (mn1 + gs) - mn1);

        int i00 = b0 * res + b1;
        int i01 = i00 + 1;
        int i10 = i00 + res;
        int i11 = i00 + res + 1;

        const float2* tb = (const float2*)tables + (size_t)lvl * TSIZE;
        float2 e00 = __ldg(tb + i00);
        float2 e01 = __ldg(tb + i01);
        float2 e10 = __ldg(tb + i10);
        float2 e11 = __ldg(tb + i11);

        float om1 = 1.0f - w1, om0 = 1.0f - w0;
        float c0x = e00.x * om1 + e01.x * w1;
        float c1x = e10.x * om1 + e11.x * w1;
        float c0y = e00.y * om1 + e01.y * w1;
        float c1y = e10.y * om1 + e11.y * w1;

        s_f[tid * 33 + 2 * lvl]     = c0x * om0 + c1x * w0;
        s_f[tid * 33 + 2 * lvl + 1] = c0y * om0 + c1y * w0;

        if (valid) {
            *(float4*)(out + idxbase + ((size_t)lvl * npts + p) * 4) =
                make_float4((float)i00, (float)i01, (float)i10, (float)i11);
        }
    }

    // ---------------- consistent-hash levels 12..15 ----------------
#pragma unroll
    for (int li = 0; li < NCONS; li++) {
        const int   lvl = NDENSE + li;
        const int   res = g_cp.res[li];
        const float gs  = g_cp.gs[li];

        float q0  = div_full(x0, gs);
        float q1  = div_full(x1, gs);
        float b0f = floorf(q0), b1f = floorf(q1);
        int   b0  = (int)b0f,   b1  = (int)b1f;
        float mn0 = b0f * gs,   mn1 = b1f * gs;
        float w0  = __fdiv_rn(x0 - mn0, (mn0 + gs) - mn0);
        float w1  = __fdiv_rn(x1 - mn1, (mn1 + gs) - mn1);

        unsigned g0 = (unsigned)b0, g1 = (unsigned)b1;
        unsigned h00 = (g0        ^ (g1        * HPRIME)) & HMASK;
        unsigned h01 = (g0        ^ ((g1 + 1u) * HPRIME)) & HMASK;
        unsigned h10 = ((g0 + 1u) ^ (g1        * HPRIME)) & HMASK;
        unsigned h11 = ((g0 + 1u) ^ ((g1 + 1u) * HPRIME)) & HMASK;

        int i00, i01, i10, i11;
        if ((unsigned)b0 < (unsigned)res && (unsigned)b1 < (unsigned)res) {
            // All 4 corners present in the table => searchsorted returns the
            // hash itself (proven: tk[k]=h[k]+h[k+1] sorted, first occurrence).
            i00 = (int)h00; i01 = (int)h01; i10 = (int)h10; i11 = (int)h11;
        } else {
            long long ro = (long long)li * maxP;
            int n = g_cp.n[li];
            i00 = cons_lookup(tk, tv, ro, n, h00);
            i01 = cons_lookup(tk, tv, ro, n, h01);
            i10 = cons_lookup(tk, tv, ro, n, h10);
            i11 = cons_lookup(tk, tv, ro, n, h11);
        }

        const float2* tb = (const float2*)tables + (size_t)lvl * TSIZE;
        float2 e00 = __ldg(tb + i00);
        float2 e01 = __ldg(tb + i01);
        float2 e10 = __ldg(tb + i10);
        float2 e11 = __ldg(tb + i11);

        float om1 = 1.0f - w1, om0 = 1.0f - w0;
        float c0x = e00.x * om1 + e01.x * w1;
        float c1x = e10.x * om1 + e11.x * w1;
        float c0y = e00.y * om1 + e01.y * w1;
        float c1y = e10.y * om1 + e11.y * w1;

        s_f[tid * 33 + 2 * lvl]     = c0x * om0 + c1x * w0;
        s_f[tid * 33 + 2 * lvl + 1] = c0y * om0 + c1y * w0;

        if (valid) {
            *(float4*)(out + idxbase + ((size_t)lvl * npts + p) * 4) =
                make_float4((float)i00, (float)i01, (float)i10, (float)i11);
        }
    }

    // ---------------- coalesced feature store via smem transpose ----------------
    __syncthreads();
    const int warp  = tid >> 5;
    const int lane  = tid & 31;
    const int wbase = blockIdx.x * BLK + warp * 32;
#pragma unroll
    for (int j = 0; j < 8; j++) {
        int off = j * 128 + lane * 4;
        int pi  = off >> 5;
        int fo  = off & 31;
        int p2  = wbase + pi;
        if (p2 < npts) {
            int sb = (warp * 32 + pi) * 33 + fo;
            float4 v = make_float4(s_f[sb], s_f[sb + 1], s_f[sb + 2], s_f[sb + 3]);
            *(float4*)(out + (size_t)p2 * 32 + fo) = v;
        }
    }
}

extern "C" void kernel_launch(void* const* d_in, const int* in_sizes, int n_in,
                              void* d_out, int out_size)
{
    const float* x       = (const float*)d_in[0];
    const float* tables  = (const float*)d_in[1];
    const int*   tk      = (const int*)d_in[2];
    const int*   tv      = (const int*)d_in[3];
    const int*   lengths = (const int*)d_in[4];

    int L    = in_sizes[4];
    int maxP = in_sizes[2] / (L > 0 ? L : 1);
    int npts = in_sizes[0] / 2;

    setup_kernel<<<1, 32>>>(lengths, L);

    int blocks = (npts + BLK - 1) / BLK;
    hashgrid_kernel<<<blocks, BLK>>>(x, tables, tk, tv, maxP, (float*)d_out, npts);
}

// round 3
// speedup vs baseline: 1.4402x; 1.4402x over previous
#include <cuda_runtime.h>
#include <math.h>

#define NLEV   16
#define NDENSE 12
#define NCONS  4
#define TSIZE  524288
#define HPRIME 2654435761u
#define HMASK  524287u
#define BLK    256

// Dense-level resolutions (float32 np.power chain margins all >> accumulated ulp error).
__device__ __constant__ int   RESD[NDENSE] = {16,22,30,42,58,80,111,153,212,294,406,561};
__device__ __constant__ float GSD[NDENSE] = {
    (float)(2048.0/16.0),  (float)(2048.0/22.0),  (float)(2048.0/30.0),
    (float)(2048.0/42.0),  (float)(2048.0/58.0),  (float)(2048.0/80.0),
    (float)(2048.0/111.0), (float)(2048.0/153.0), (float)(2048.0/212.0),
    (float)(2048.0/294.0), (float)(2048.0/406.0), (float)(2048.0/561.0)
};

// Consistent-hash level params recovered exactly from lengths (levels 14/15 sit
// within float32 noise of a floor boundary, so they cannot be hardcoded).
struct ConsParams { int res[NCONS]; int n[NCONS]; float gs[NCONS]; };
__device__ ConsParams g_cp;

__global__ void setup_kernel(const int* __restrict__ lengths, int L)
{
    if (threadIdx.x == 0 && blockIdx.x == 0) {
        for (int i = 0; i < NCONS; i++) {
            int li  = (i < L) ? i : (L - 1);
            int len = lengths[li];                    // (res+1)^2
            int res = (int)(sqrt((double)len) + 0.5) - 1;
            g_cp.res[i] = res;
            g_cp.n[i]   = len;
            g_cp.gs[i]  = (float)(2048.0 / (double)res);
        }
    }
}

// XLA:GPU emits approximate full-range division (div.full.f32) for f32 divide.
// Required for bit-exact bl = floor(x/gs) at cell boundaries.
__device__ __forceinline__ float div_full(float a, float b)
{
    float r;
    asm("div.full.f32 %0, %1, %2;" : "=f"(r) : "f"(a), "f"(b));
    return r;
}

// Exact replica of jnp.searchsorted(tk_row, 2h) -> where(k==n,0,k) -> tv[k].
// Only reached when a corner coordinate exceeds res (rounding edge case).
__device__ __forceinline__ int cons_lookup(const int* __restrict__ tk,
                                           const int* __restrict__ tv,
                                           long long rowoff, int n, unsigned h)
{
    int q  = 2 * (int)h;
    int lo = 0, hi = n;
    while (lo < hi) {
        int mid = (lo + hi) >> 1;
        if (__ldg(tk + rowoff + mid) < q) lo = mid + 1; else hi = mid;
    }
    if (lo == n) lo = 0;
    return __ldg(tv + rowoff + lo);
}

// 4 threads per point. Lane-role g = tid&3 handles levels {3g, 3g+1, 3g+2, 12+g}:
// every thread does 3 dense + 1 hash level -> no warp divergence. A warp covers
// 8 consecutive points; each point's 32 feats = one 128B line, so feat stores
// touch <= 8 lines per instruction regardless of intra-point scatter.
__global__ __launch_bounds__(BLK)
void hashgrid_kernel(const float* __restrict__ x,
                     const float* __restrict__ tables,
                     const int*   __restrict__ tk,
                     const int*   __restrict__ tv,
                     int maxP,
                     float* __restrict__ out,
                     int npts)
{
    const int t = blockIdx.x * BLK + threadIdx.x;
    const int p = t >> 2;
    const int g = t & 3;
    const bool valid = (p < npts);
    const int  pl = valid ? p : (npts - 1);

    const float2 xv = __ldg((const float2*)x + pl);
    const float x0 = xv.x, x1 = xv.y;
    const size_t idxbase = (size_t)npts * 32;

    int   lvls[4];
    lvls[0] = 3 * g; lvls[1] = 3 * g + 1; lvls[2] = 3 * g + 2; lvls[3] = 12 + g;

    int   idxs[16];
    float w0s[4], w1s[4];

    // ---- phase 1: all indices + weights (no memory latency on critical path) ----
#pragma unroll
    for (int j = 0; j < 3; j++) {
        const int   l   = lvls[j];
        const int   res = RESD[l];
        const float gs  = GSD[l];

        float q0  = div_full(x0, gs);
        float q1  = div_full(x1, gs);
        float b0f = floorf(q0), b1f = floorf(q1);
        int   b0  = (int)b0f,   b1  = (int)b1f;
        float mn0 = b0f * gs,   mn1 = b1f * gs;
        w0s[j] = __fdiv_rn(x0 - mn0, (mn0 + gs) - mn0);
        w1s[j] = __fdiv_rn(x1 - mn1, (mn1 + gs) - mn1);

        int i00 = b0 * res + b1;
        idxs[4 * j + 0] = i00;
        idxs[4 * j + 1] = i00 + 1;
        idxs[4 * j + 2] = i00 + res;
        idxs[4 * j + 3] = i00 + res + 1;
    }
    {   // hash level li = g
        const int   li  = g;
        const int   res = g_cp.res[li];
        const float gs  = g_cp.gs[li];

        float q0  = div_full(x0, gs);
        float q1  = div_full(x1, gs);
        float b0f = floorf(q0), b1f = floorf(q1);
        int   b0  = (int)b0f,   b1  = (int)b1f;
        float mn0 = b0f * gs,   mn1 = b1f * gs;
        w0s[3] = __fdiv_rn(x0 - mn0, (mn0 + gs) - mn0);
        w1s[3] = __fdiv_rn(x1 - mn1, (mn1 + gs) - mn1);

        unsigned g0 = (unsigned)b0, g1 = (unsigned)b1;
        unsigned h00 = (g0        ^ (g1        * HPRIME)) & HMASK;
        unsigned h01 = (g0        ^ ((g1 + 1u) * HPRIME)) & HMASK;
        unsigned h10 = ((g0 + 1u) ^ (g1        * HPRIME)) & HMASK;
        unsigned h11 = ((g0 + 1u) ^ ((g1 + 1u) * HPRIME)) & HMASK;

        if ((unsigned)b0 < (unsigned)res && (unsigned)b1 < (unsigned)res) {
            // All 4 corners present in the table => searchsorted returns the hash itself.
            idxs[12] = (int)h00; idxs[13] = (int)h01;
            idxs[14] = (int)h10; idxs[15] = (int)h11;
        } else {
            long long ro = (long long)li * maxP;
            int n = g_cp.n[li];
            idxs[12] = cons_lookup(tk, tv, ro, n, h00);
            idxs[13] = cons_lookup(tk, tv, ro, n, h01);
            idxs[14] = cons_lookup(tk, tv, ro, n, h10);
            idxs[15] = cons_lookup(tk, tv, ro, n, h11);
        }
    }

    // ---- phase 2: issue all 16 gathers back-to-back (MLP ~16 per thread) ----
    float2 e[16];
#pragma unroll
    for (int j = 0; j < 4; j++) {
        const float2* tb = (const float2*)tables + (size_t)lvls[j] * TSIZE;
#pragma unroll
        for (int k = 0; k < 4; k++)
            e[4 * j + k] = __ldg(tb + idxs[4 * j + k]);
    }

    // ---- phase 3: idx stores (independent of gathers; overlaps their latency) ----
    if (valid) {
#pragma unroll
        for (int j = 0; j < 4; j++) {
            float4 v = make_float4((float)idxs[4 * j + 0], (float)idxs[4 * j + 1],
                                   (float)idxs[4 * j + 2], (float)idxs[4 * j + 3]);
            __stcs((float4*)(out + idxbase + ((size_t)lvls[j] * npts + p) * 4), v);
        }
    }

    // ---- phase 4: interpolate + streaming feat stores ----
    if (valid) {
#pragma unroll
        for (int j = 0; j < 4; j++) {
            float w0 = w0s[j], w1 = w1s[j];
            float om0 = 1.0f - w0, om1 = 1.0f - w1;
            float2 e00 = e[4 * j + 0], e01 = e[4 * j + 1];
            float2 e10 = e[4 * j + 2], e11 = e[4 * j + 3];
            float c0x = e00.x * om1 + e01.x * w1;
            float c1x = e10.x * om1 + e11.x * w1;
            float c0y = e00.y * om1 + e01.y * w1;
            float c1y = e10.y * om1 + e11.y * w1;
            float2 f = make_float2(c0x * om0 + c1x * w0, c0y * om0 + c1y * w0);
            __stcs((float2*)(out + (size_t)p * 32 + 2 * lvls[j]), f);
        }
    }
}

extern "C" void kernel_launch(void* const* d_in, const int* in_sizes, int n_in,
                              void* d_out, int out_size)
{
    const float* x       = (const float*)d_in[0];
    const float* tables  = (const float*)d_in[1];
    const int*   tk      = (const int*)d_in[2];
    const int*   tv      = (const int*)d_in[3];
    const int*   lengths = (const int*)d_in[4];

    int L    = in_sizes[4];
    int maxP = in_sizes[2] / (L > 0 ? L : 1);
    int npts = in_sizes[0] / 2;

    setup_kernel<<<1, 32>>>(lengths, L);

    long long nthreads = 4LL * npts;
    int blocks = (int)((nthreads + BLK - 1) / BLK);
    hashgrid_kernel<<<blocks, BLK>>>(x, tables, tk, tv, maxP, (float*)d_out, npts);
}

// round 4
// speedup vs baseline: 1.5460x; 1.0735x over previous
#include <cuda_runtime.h>
#include <math.h>

#define NLEV   16
#define NDENSE 12
#define NCONS  4
#define TSIZE  524288
#define HPRIME 2654435761u
#define HMASK  524287u
#define BLK    256

// Unified per-level params (dense levels hardcoded, hash levels from lengths).
struct LevelParams { float gs; int res; int n; int pad; };
__device__ LevelParams g_lp[NLEV];

__global__ void setup_kernel(const int* __restrict__ lengths, int L)
{
    if (threadIdx.x == 0 && blockIdx.x == 0) {
        // Dense resolutions: float32 np.power chain, margins all >> ulp error.
        const int rd[NDENSE] = {16,22,30,42,58,80,111,153,212,294,406,561};
        for (int i = 0; i < NDENSE; i++) {
            g_lp[i].res = rd[i];
            g_lp[i].gs  = (float)(2048.0 / (double)rd[i]);
            g_lp[i].n   = 0;
        }
        for (int i = 0; i < NCONS; i++) {
            int li  = (i < L) ? i : (L - 1);
            int len = lengths[li];                    // (res+1)^2
            int res = (int)(sqrt((double)len) + 0.5) - 1;
            g_lp[NDENSE + i].res = res;
            g_lp[NDENSE + i].n   = len;
            g_lp[NDENSE + i].gs  = (float)(2048.0 / (double)res);
        }
    }
}

// XLA:GPU emits approximate full-range division (div.full.f32) for f32 divide.
// Required for bit-exact bl = floor(x/gs) at cell boundaries.
__device__ __forceinline__ float div_full(float a, float b)
{
    float r;
    asm("div.full.f32 %0, %1, %2;" : "=f"(r) : "f"(a), "f"(b));
    return r;
}

// Exact replica of jnp.searchsorted(tk_row, 2h) -> where(k==n,0,k) -> tv[k].
// Only reached when a corner coordinate exceeds res (rounding edge case).
__device__ __forceinline__ int cons_lookup(const int* __restrict__ tk,
                                           const int* __restrict__ tv,
                                           long long rowoff, int n, unsigned h)
{
    int q  = 2 * (int)h;
    int lo = 0, hi = n;
    while (lo < hi) {
        int mid = (lo + hi) >> 1;
        if (__ldg(tk + rowoff + mid) < q) lo = mid + 1; else hi = mid;
    }
    if (lo == n) lo = 0;
    return __ldg(tv + rowoff + lo);
}

// 4 threads per point; lane role g = tid&3 owns levels {4g..4g+3}.
// g<3 lanes: all-dense levels (corner pairs adjacent in memory -> LDG.128 trick).
// g=3 lane: all 4 hash levels (independent random corners -> LDG.64 x4).
// Feats of lane g are a CONTIGUOUS 8-float slice of the point's row -> 2x STG.128.
__global__ __launch_bounds__(BLK)
void hashgrid_kernel(const float* __restrict__ x,
                     const float* __restrict__ tables,
                     const int*   __restrict__ tk,
                     const int*   __restrict__ tv,
                     int maxP,
                     float* __restrict__ out,
                     int npts)
{
    const int t = blockIdx.x * BLK + threadIdx.x;
    const int p = t >> 2;
    const int g = t & 3;
    const bool valid = (p < npts);
    const int  pl = valid ? p : (npts - 1);

    const float2 xv = __ldg((const float2*)x + pl);
    const float x0 = xv.x, x1 = xv.y;
    const size_t idxbase = (size_t)npts * 32;
    const int lvl0 = 4 * g;

    int   idxs[16];
    float w0s[4], w1s[4];

    // ---- phase 1: indices + weights for this lane's 4 levels ----
#pragma unroll
    for (int j = 0; j < 4; j++) {
        const int lvl = lvl0 + j;
        const LevelParams lp = g_lp[lvl];
        const int   res = lp.res;
        const float gs  = lp.gs;

        float q0  = div_full(x0, gs);
        float q1  = div_full(x1, gs);
        float b0f = floorf(q0), b1f = floorf(q1);
        int   b0  = (int)b0f,   b1  = (int)b1f;
        float mn0 = b0f * gs,   mn1 = b1f * gs;
        w0s[j] = __fdiv_rn(x0 - mn0, (mn0 + gs) - mn0);
        w1s[j] = __fdiv_rn(x1 - mn1, (mn1 + gs) - mn1);

        if (lvl < NDENSE) {
            int i00 = b0 * res + b1;
            idxs[4 * j + 0] = i00;
            idxs[4 * j + 1] = i00 + 1;
            idxs[4 * j + 2] = i00 + res;
            idxs[4 * j + 3] = i00 + res + 1;
        } else {
            unsigned g0 = (unsigned)b0, g1 = (unsigned)b1;
            unsigned h00 = (g0        ^ (g1        * HPRIME)) & HMASK;
            unsigned h01 = (g0        ^ ((g1 + 1u) * HPRIME)) & HMASK;
            unsigned h10 = ((g0 + 1u) ^ (g1        * HPRIME)) & HMASK;
            unsigned h11 = ((g0 + 1u) ^ ((g1 + 1u) * HPRIME)) & HMASK;

            if ((unsigned)b0 < (unsigned)res && (unsigned)b1 < (unsigned)res) {
                // All 4 corners present in table => searchsorted returns the hash.
                idxs[4 * j + 0] = (int)h00; idxs[4 * j + 1] = (int)h01;
                idxs[4 * j + 2] = (int)h10; idxs[4 * j + 3] = (int)h11;
            } else {
                int li = lvl - NDENSE;
                long long ro = (long long)li * maxP;
                int n = lp.n;
                idxs[4 * j + 0] = cons_lookup(tk, tv, ro, n, h00);
                idxs[4 * j + 1] = cons_lookup(tk, tv, ro, n, h01);
                idxs[4 * j + 2] = cons_lookup(tk, tv, ro, n, h10);
                idxs[4 * j + 3] = cons_lookup(tk, tv, ro, n, h11);
            }
        }
    }

    // ---- phase 2: gathers, issued back-to-back for MLP ----
    float2 e[16];
    if (g < 3) {
        // Dense: corner pairs (i00,i01) and (i10,i11) are adjacent 8B entries.
        // Aligned-down LDG.128 covers the pair when i00 even; odd case adds one
        // predicated LDG.64. Expected line-accesses per pair: 1.5 vs 2.0.
#pragma unroll
        for (int j = 0; j < 4; j++) {
            const int lvl = lvl0 + j;
            const float2* tb  = (const float2*)tables + (size_t)lvl * TSIZE;
            const float4* tb4 = (const float4*)tb;
#pragma unroll
            for (int pr = 0; pr < 2; pr++) {
                int ibase = idxs[4 * j + 2 * pr];          // i00 or i10
                float4 lo = __ldg(tb4 + (ibase >> 1));
                float2 hi = make_float2(0.f, 0.f);
                bool odd = (ibase & 1);
                if (odd) hi = __ldg(tb + ibase + 1);
                float2 e_lo = odd ? make_float2(lo.z, lo.w) : make_float2(lo.x, lo.y);
                float2 e_hi = odd ? hi                       : make_float2(lo.z, lo.w);
                e[4 * j + 2 * pr]     = e_lo;
                e[4 * j + 2 * pr + 1] = e_hi;
            }
        }
    } else {
        // Hash levels: 4 independent random corners.
#pragma unroll
        for (int j = 0; j < 4; j++) {
            const int lvl = lvl0 + j;
            const float2* tb = (const float2*)tables + (size_t)lvl * TSIZE;
#pragma unroll
            for (int k = 0; k < 4; k++)
                e[4 * j + k] = __ldg(tb + idxs[4 * j + k]);
        }
    }

    // ---- phase 3: idx stores (overlap gather latency) ----
    if (valid) {
#pragma unroll
        for (int j = 0; j < 4; j++) {
            const int lvl = lvl0 + j;
            float4 v = make_float4((float)idxs[4 * j + 0], (float)idxs[4 * j + 1],
                                   (float)idxs[4 * j + 2], (float)idxs[4 * j + 3]);
            __stcs((float4*)(out + idxbase + ((size_t)lvl * npts + p) * 4), v);
        }
    }

    // ---- phase 4: interpolate + two contiguous STG.128 feat stores ----
    if (valid) {
        float f[8];
#pragma unroll
        for (int j = 0; j < 4; j++) {
            float w0 = w0s[j], w1 = w1s[j];
            float om0 = 1.0f - w0, om1 = 1.0f - w1;
            float2 e00 = e[4 * j + 0], e01 = e[4 * j + 1];
            float2 e10 = e[4 * j + 2], e11 = e[4 * j + 3];
            float c0x = e00.x * om1 + e01.x * w1;
            float c1x = e10.x * om1 + e11.x * w1;
            float c0y = e00.y * om1 + e01.y * w1;
            float c1y = e10.y * om1 + e11.y * w1;
            f[2 * j]     = c0x * om0 + c1x * w0;
            f[2 * j + 1] = c0y * om0 + c1y * w0;
        }
        float* dst = out + (size_t)p * 32 + 8 * g;     // contiguous lane slice
        __stcs((float4*)dst,       make_float4(f[0], f[1], f[2], f[3]));
        __stcs((float4*)(dst + 4), make_float4(f[4], f[5], f[6], f[7]));
    }
}

extern "C" void kernel_launch(void* const* d_in, const int* in_sizes, int n_in,
                              void* d_out, int out_size)
{
    const float* x       = (const float*)d_in[0];
    const float* tables  = (const float*)d_in[1];
    const int*   tk      = (const int*)d_in[2];
    const int*   tv      = (const int*)d_in[3];
    const int*   lengths = (const int*)d_in[4];

    int L    = in_sizes[4];
    int maxP = in_sizes[2] / (L > 0 ? L : 1);
    int npts = in_sizes[0] / 2;

    setup_kernel<<<1, 32>>>(lengths, L);

    long long nthreads = 4LL * npts;
    int blocks = (int)((nthreads + BLK - 1) / BLK);
    hashgrid_kernel<<<blocks, BLK>>>(x, tables, tk, tv, maxP, (float*)d_out, npts);
}